// round 15
// baseline (speedup 1.0000x reference)
#include <cuda_runtime.h>
#include <cuda_bf16.h>
#include <math.h>

#define T 512
#define B 128
#define D 256
#define H 256
#define TBD (T * B * D)

// Scratch: input projections per direction, bf16 split arrays for proj GEMM.
__device__ float g_xw[2][(size_t)T * B * H];
__device__ uint4 g_xh4[TBD / 8];            // x hi bf16, [m][k] k-major, 8/uint4
__device__ uint4 g_xl4[TBD / 8];            // x lo residual bf16
__device__ uint4 g_wth4[2][H * D / 8];      // W^T hi bf16, [n][k] k-major
__device__ uint4 g_wtl4[2][H * D / 8];      // W^T lo residual

typedef unsigned long long u64;
typedef unsigned int u32;

__device__ __forceinline__ u64 pk2(float lo, float hi) {
    u64 r; asm("mov.b64 %0, {%1, %2};" : "=l"(r) : "f"(lo), "f"(hi)); return r;
}
__device__ __forceinline__ void upk2(float& lo, float& hi, u64 v) {
    asm("mov.b64 {%0, %1}, %2;" : "=f"(lo), "=f"(hi) : "l"(v));
}
__device__ __forceinline__ void ffma2(u64& acc, u64 a, u64 b) {
    asm("fma.rn.f32x2 %0, %1, %2, %3;" : "=l"(acc) : "l"(a), "l"(b), "l"(acc));
}
__device__ __forceinline__ float tanh_fast(float x) {
    float y; asm("tanh.approx.f32 %0, %1;" : "=f"(y) : "f"(x)); return y;
}
__device__ __forceinline__ u64 bfpair(u32 w) {
    u64 r;
    asm("{ .reg .b32 lo, hi;\n"
        "  shl.b32 lo, %1, 16;\n"
        "  and.b32 hi, %1, 0xffff0000;\n"
        "  mov.b64 %0, {lo, hi}; }" : "=l"(r) : "r"(w));
    return r;
}
// pack two f32 into bf16x2: lo16 = cvt(vlo), hi16 = cvt(vhi)
__device__ __forceinline__ u32 cvt_bf16x2(float vhi, float vlo) {
    u32 d; asm("cvt.rn.bf16x2.f32 %0, %1, %2;" : "=r"(d) : "f"(vhi), "f"(vlo));
    return d;
}
__device__ __forceinline__ void cp_async16(void* smem_dst, const void* gptr) {
    u32 saddr = (u32)__cvta_generic_to_shared(smem_dst);
    asm volatile("cp.async.cg.shared.global [%0], [%1], 16;\n" :: "r"(saddr), "l"(gptr));
}

// mma.sync m16n8k16 row.col bf16 -> f32 accum
__device__ __forceinline__ void mma_bf16(float* c, u32 a0, u32 a1, u32 a2, u32 a3,
                                         u32 b0, u32 b1) {
    asm volatile(
        "mma.sync.aligned.m16n8k16.row.col.f32.bf16.bf16.f32 "
        "{%0,%1,%2,%3}, {%4,%5,%6,%7}, {%8,%9}, {%0,%1,%2,%3};"
        : "+f"(c[0]), "+f"(c[1]), "+f"(c[2]), "+f"(c[3])
        : "r"(a0), "r"(a1), "r"(a2), "r"(a3), "r"(b0), "r"(b1));
}

// ---------------------------------------------------------------------------
// Convert kernels (run once, before proj)
// ---------------------------------------------------------------------------
__global__ __launch_bounds__(256) void cvt_x_kernel(const float* __restrict__ inp)
{
    size_t i = (size_t)blockIdx.x * 256 + threadIdx.x;   // over TBD/8
    const float4* p = (const float4*)inp + i * 2;
    float4 v0 = p[0], v1 = p[1];
    u32 h0 = cvt_bf16x2(v0.y, v0.x);
    u32 h1 = cvt_bf16x2(v0.w, v0.z);
    u32 h2 = cvt_bf16x2(v1.y, v1.x);
    u32 h3 = cvt_bf16x2(v1.w, v1.z);
    u32 l0, l1, l2, l3;
    {
        float a0 = __uint_as_float(h0 << 16), a1 = __uint_as_float(h0 & 0xffff0000u);
        l0 = cvt_bf16x2(v0.y - a1, v0.x - a0);
        float b0 = __uint_as_float(h1 << 16), b1 = __uint_as_float(h1 & 0xffff0000u);
        l1 = cvt_bf16x2(v0.w - b1, v0.z - b0);
        float c0 = __uint_as_float(h2 << 16), c1 = __uint_as_float(h2 & 0xffff0000u);
        l2 = cvt_bf16x2(v1.y - c1, v1.x - c0);
        float d0 = __uint_as_float(h3 << 16), d1 = __uint_as_float(h3 & 0xffff0000u);
        l3 = cvt_bf16x2(v1.w - d1, v1.z - d0);
    }
    g_xh4[i] = make_uint4(h0, h1, h2, h3);
    g_xl4[i] = make_uint4(l0, l1, l2, l3);
}

__global__ __launch_bounds__(256) void cvt_w_kernel(const float* __restrict__ Wf,
                                                    const float* __restrict__ Wb)
{
    int i = blockIdx.x * 256 + threadIdx.x;     // over 2 * H * (D/8)
    const int per = H * (D / 8);
    int dir = i / per;
    int idx = i - dir * per;
    int n  = idx >> 5;          // D/8 = 32
    int kc = idx & 31;
    int k0 = kc * 8;
    const float* W = dir ? Wb : Wf;
    u32 hh[4], ll[4];
    #pragma unroll
    for (int q = 0; q < 4; q++) {
        float w0 = W[(size_t)(k0 + 2 * q) * H + n];
        float w1 = W[(size_t)(k0 + 2 * q + 1) * H + n];
        u32 h = cvt_bf16x2(w1, w0);
        float e0 = __uint_as_float(h << 16);
        float e1 = __uint_as_float(h & 0xffff0000u);
        hh[q] = h;
        ll[q] = cvt_bf16x2(w1 - e1, w0 - e0);
    }
    g_wth4[dir][idx] = make_uint4(hh[0], hh[1], hh[2], hh[3]);
    g_wtl4[dir][idx] = make_uint4(ll[0], ll[1], ll[2], ll[3]);
}

// ---------------------------------------------------------------------------
// Kernel 1: xw = x @ W + b via HMMA bf16 3-term split.
// SINGLE 64KB stage -> 2 CTAs/SM; cross-CTA interleaving hides staging.
// CTA tile 128m x 128n, 8 warps (4M x 2N). Verified swizzle layout.
// ---------------------------------------------------------------------------
#define SM_AH 0
#define SM_AL 16384
#define SM_BH 32768
#define SM_BL 49152
#define PROJ_SMEM 65536               // one stage, 64KB

__device__ __forceinline__ u32 sw_off(int row, int k) {
    return (u32)(row * 128 + (((k >> 3) ^ (row & 7)) << 4) + (k & 7) * 2);
}

__global__ __launch_bounds__(256, 2) void proj_tc_kernel(
    const float* __restrict__ bfp, const float* __restrict__ bbp)
{
    extern __shared__ char smem[];

    const int dir = blockIdx.z;
    const float* __restrict__ bias = dir ? bbp : bfp;
    float* __restrict__ out = g_xw[dir];
    const uint4* __restrict__ wth = g_wth4[dir];
    const uint4* __restrict__ wtl = g_wtl4[dir];

    const int m0  = blockIdx.x * 128;
    const int n0t = blockIdx.y * 128;

    const int tid  = threadIdx.x;
    const int lane = tid & 31;
    const int wid  = tid >> 5;
    const int gid  = lane >> 2;
    const int tig  = lane & 3;
    const int wm   = wid & 3;
    const int wn   = wid >> 2;
    const int rbase = 32 * wm;
    const int nbase = 64 * wn;

    float acc[2][8][4];
    #pragma unroll
    for (int mf = 0; mf < 2; mf++)
        #pragma unroll
        for (int nf = 0; nf < 8; nf++)
            #pragma unroll
            for (int q = 0; q < 4; q++) acc[mf][nf][q] = 0.f;

    for (int c = 0; c < 4; c++) {
        __syncthreads();   // previous chunk's math done before overwrite

        // stage chunk c: 1024 (row, kc) 16B chunks per tile
        #pragma unroll
        for (int i = tid; i < 1024; i += 256) {
            int row = i >> 3, kc = i & 7;
            u32 dst = (u32)(row * 128 + ((kc ^ (row & 7)) << 4));
            size_t srcA = (size_t)(m0 + row) * 32 + c * 8 + kc;
            size_t srcB = (size_t)(n0t + row) * 32 + c * 8 + kc;
            cp_async16(smem + SM_AH + dst, &g_xh4[srcA]);
            cp_async16(smem + SM_AL + dst, &g_xl4[srcA]);
            cp_async16(smem + SM_BH + dst, &wth[srcB]);
            cp_async16(smem + SM_BL + dst, &wtl[srcB]);
        }
        asm volatile("cp.async.commit_group;\n");
        asm volatile("cp.async.wait_group 0;\n");
        __syncthreads();

        #pragma unroll
        for (int ks = 0; ks < 4; ks++) {
            const int k0 = 16 * ks;
            u32 ah[2][4], al[2][4];
            #pragma unroll
            for (int mf = 0; mf < 2; mf++) {
                int r0 = rbase + 16 * mf + gid;
                int r1 = r0 + 8;
                u32 o00 = sw_off(r0, k0 + 2 * tig);
                u32 o10 = sw_off(r1, k0 + 2 * tig);
                u32 o01 = sw_off(r0, k0 + 8 + 2 * tig);
                u32 o11 = sw_off(r1, k0 + 8 + 2 * tig);
                ah[mf][0] = *(const u32*)(smem + SM_AH + o00);
                ah[mf][1] = *(const u32*)(smem + SM_AH + o10);
                ah[mf][2] = *(const u32*)(smem + SM_AH + o01);
                ah[mf][3] = *(const u32*)(smem + SM_AH + o11);
                al[mf][0] = *(const u32*)(smem + SM_AL + o00);
                al[mf][1] = *(const u32*)(smem + SM_AL + o10);
                al[mf][2] = *(const u32*)(smem + SM_AL + o01);
                al[mf][3] = *(const u32*)(smem + SM_AL + o11);
            }
            #pragma unroll
            for (int nf = 0; nf < 8; nf++) {
                int n = nbase + 8 * nf + gid;
                u32 ob0 = sw_off(n, k0 + 2 * tig);
                u32 ob1 = sw_off(n, k0 + 8 + 2 * tig);
                u32 bh0 = *(const u32*)(smem + SM_BH + ob0);
                u32 bh1 = *(const u32*)(smem + SM_BH + ob1);
                u32 bl0 = *(const u32*)(smem + SM_BL + ob0);
                u32 bl1 = *(const u32*)(smem + SM_BL + ob1);
                #pragma unroll
                for (int mf = 0; mf < 2; mf++) {
                    mma_bf16(acc[mf][nf], ah[mf][0], ah[mf][1], ah[mf][2], ah[mf][3], bh0, bh1);
                    mma_bf16(acc[mf][nf], ah[mf][0], ah[mf][1], ah[mf][2], ah[mf][3], bl0, bl1);
                    mma_bf16(acc[mf][nf], al[mf][0], al[mf][1], al[mf][2], al[mf][3], bh0, bh1);
                }
            }
        }
    }

    // epilogue: bias + store
    #pragma unroll
    for (int nf = 0; nf < 8; nf++) {
        int ncol = n0t + nbase + 8 * nf + 2 * tig;
        float2 bv = *(const float2*)&bias[ncol];
        #pragma unroll
        for (int mf = 0; mf < 2; mf++) {
            int row0 = m0 + rbase + 16 * mf + gid;
            int row1 = row0 + 8;
            *(float2*)&out[(size_t)row0 * H + ncol] =
                make_float2(acc[mf][nf][0] + bv.x, acc[mf][nf][1] + bv.y);
            *(float2*)&out[(size_t)row1 * H + ncol] =
                make_float2(acc[mf][nf][2] + bv.x, acc[mf][nf][3] + bv.y);
        }
    }
}

// ---------------------------------------------------------------------------
// Kernel 2: recurrent scan. Round-7 structure; W storage now tiered to kill
// the unpack ALU (values identical — bf16->fp32 expansion is exact):
//   k [0,128)  : fp32 pairs in 128 registers (no ALU, no LDS)
//   k [128,224): bf16-packed in 12 uint4 regs (96 ALU)
//   k [224,256): bf16-packed in smem, 4 uint4/thread (16KB, 4 LDS, 32 ALU)
// h double-buffered in smem; one barrier/step; fma.rn.f32x2 math.
// ---------------------------------------------------------------------------
#define NFPP 64     // fp32 pairs in regs (128 k)
#define NBRG 12     // bf16 uint4 in regs  (96 k)
#define NBSM 4      // bf16 uint4 in smem  (32 k)

__global__ __launch_bounds__(256, 1) void scan_kernel(
    const float* __restrict__ Whh_f,
    const float* __restrict__ Whh_b,
    float* __restrict__ out)
{
    __shared__ float hbuf[2 * 2 * H];       // 4KB
    __shared__ uint4 Wsm[NBSM][H];          // 16KB

    const int blk  = blockIdx.x;
    const int dir  = blk >> 6;
    const int brow = (blk & 63) * 2;
    const float* __restrict__ Whh = dir ? Whh_b : Whh_f;
    const float* __restrict__ xw  = g_xw[dir];
    const int j = threadIdx.x;

    u64   wfp[NFPP];      // 128 regs: fp32 pairs, k in [0,128)
    uint4 wreg[NBRG];     // 48 regs: bf16 packed, k in [128,224)

    #pragma unroll
    for (int k8 = 0; k8 < 32; k8++) {
        u32 wrd[4];
        #pragma unroll
        for (int q = 0; q < 4; q++) {
            float w0 = Whh[(k8 * 8 + 2 * q)     * H + j];
            float w1 = Whh[(k8 * 8 + 2 * q + 1) * H + j];
            u32 b0 = (u32)__bfloat16_as_ushort(__float2bfloat16(w0));
            u32 b1 = (u32)__bfloat16_as_ushort(__float2bfloat16(w1));
            wrd[q] = (b1 << 16) | b0;
        }
        if (k8 < 16) {
            #pragma unroll
            for (int q = 0; q < 4; q++) wfp[k8 * 4 + q] = bfpair(wrd[q]);
        } else if (k8 < 16 + NBRG) {
            wreg[k8 - 16] = make_uint4(wrd[0], wrd[1], wrd[2], wrd[3]);
        } else {
            Wsm[k8 - 16 - NBRG][j] = make_uint4(wrd[0], wrd[1], wrd[2], wrd[3]);
        }
    }

    hbuf[j] = 0.f;
    hbuf[H + j] = 0.f;
    __syncthreads();

    float* __restrict__ fin = out + (size_t)T * B * 2 * H;

    int t  = dir ? (T - 1) : 0;
    const int dt = dir ? -1 : 1;
    int p = 0;
    float h0 = 0.f, h1 = 0.f;

    const float* xr = xw + ((size_t)t * B + brow) * H + j;
    float x0 = __ldg(xr);
    float x1 = __ldg(xr + H);

    for (int s = 0; s < T; s++) {
        float xn0 = 0.f, xn1 = 0.f;
        if (s + 1 < T) {
            const float* xr2 = xw + ((size_t)(t + dt) * B + brow) * H + j;
            xn0 = __ldg(xr2);
            xn1 = __ldg(xr2 + H);
        }

        const float* hr0 = hbuf + p * (2 * H);
        const float* hr1 = hr0 + H;

        u64 acc[2][4];
        #pragma unroll
        for (int r = 0; r < 2; r++)
            #pragma unroll
            for (int q = 0; q < 4; q++) acc[r][q] = 0ull;

        // ---- k [0,128): fp32-pair W in registers (no unpack)
        #pragma unroll
        for (int k8 = 0; k8 < 16; k8++) {
            ulonglong2 a0 = *(const ulonglong2*)&hr0[k8 * 8];
            ulonglong2 a1 = *(const ulonglong2*)&hr0[k8 * 8 + 4];
            ulonglong2 b0 = *(const ulonglong2*)&hr1[k8 * 8];
            ulonglong2 b1 = *(const ulonglong2*)&hr1[k8 * 8 + 4];
            ffma2(acc[0][0], a0.x, wfp[k8 * 4 + 0]);
            ffma2(acc[0][1], a0.y, wfp[k8 * 4 + 1]);
            ffma2(acc[0][2], a1.x, wfp[k8 * 4 + 2]);
            ffma2(acc[0][3], a1.y, wfp[k8 * 4 + 3]);
            ffma2(acc[1][0], b0.x, wfp[k8 * 4 + 0]);
            ffma2(acc[1][1], b0.y, wfp[k8 * 4 + 1]);
            ffma2(acc[1][2], b1.x, wfp[k8 * 4 + 2]);
            ffma2(acc[1][3], b1.y, wfp[k8 * 4 + 3]);
        }
        // ---- k [128,224): bf16 W in registers
        #pragma unroll
        for (int i = 0; i < NBRG; i++) {
            const int kb = 128 + i * 8;
            uint4 w = wreg[i];
            ulonglong2 a0 = *(const ulonglong2*)&hr0[kb];
            ulonglong2 a1 = *(const ulonglong2*)&hr0[kb + 4];
            ulonglong2 b0 = *(const ulonglong2*)&hr1[kb];
            ulonglong2 b1 = *(const ulonglong2*)&hr1[kb + 4];
            u64 w01 = bfpair(w.x);
            u64 w23 = bfpair(w.y);
            u64 w45 = bfpair(w.z);
            u64 w67 = bfpair(w.w);
            ffma2(acc[0][0], a0.x, w01);
            ffma2(acc[0][1], a0.y, w23);
            ffma2(acc[0][2], a1.x, w45);
            ffma2(acc[0][3], a1.y, w67);
            ffma2(acc[1][0], b0.x, w01);
            ffma2(acc[1][1], b0.y, w23);
            ffma2(acc[1][2], b1.x, w45);
            ffma2(acc[1][3], b1.y, w67);
        }
        // ---- k [224,256): bf16 W in smem
        #pragma unroll
        for (int i = 0; i < NBSM; i++) {
            const int kb = 224 + i * 8;
            uint4 w = Wsm[i][j];
            ulonglong2 a0 = *(const ulonglong2*)&hr0[kb];
            ulonglong2 a1 = *(const ulonglong2*)&hr0[kb + 4];
            ulonglong2 b0 = *(const ulonglong2*)&hr1[kb];
            ulonglong2 b1 = *(const ulonglong2*)&hr1[kb + 4];
            u64 w01 = bfpair(w.x);
            u64 w23 = bfpair(w.y);
            u64 w45 = bfpair(w.z);
            u64 w67 = bfpair(w.w);
            ffma2(acc[0][0], a0.x, w01);
            ffma2(acc[0][1], a0.y, w23);
            ffma2(acc[0][2], a1.x, w45);
            ffma2(acc[0][3], a1.y, w67);
            ffma2(acc[1][0], b0.x, w01);
            ffma2(acc[1][1], b0.y, w23);
            ffma2(acc[1][2], b1.x, w45);
            ffma2(acc[1][3], b1.y, w67);
        }

        float lo, hi;
        upk2(lo, hi, acc[0][0]); float s0 = x0 + lo + hi;
        upk2(lo, hi, acc[0][1]); s0 += lo + hi;
        upk2(lo, hi, acc[0][2]); s0 += lo + hi;
        upk2(lo, hi, acc[0][3]); s0 += lo + hi;
        upk2(lo, hi, acc[1][0]); float s1 = x1 + lo + hi;
        upk2(lo, hi, acc[1][1]); s1 += lo + hi;
        upk2(lo, hi, acc[1][2]); s1 += lo + hi;
        upk2(lo, hi, acc[1][3]); s1 += lo + hi;

        h0 = tanh_fast(s0);
        h1 = tanh_fast(s1);

        hbuf[(p ^ 1) * (2 * H) + j]     = h0;
        hbuf[(p ^ 1) * (2 * H) + H + j] = h1;

        size_t ob = ((size_t)t * B + brow) * (2 * H) + (size_t)dir * H + j;
        out[ob]         = h0;
        out[ob + 2 * H] = h1;

        __syncthreads();
        p ^= 1;
        t += dt;
        x0 = xn0;
        x1 = xn1;
    }

    size_t fb = (size_t)dir * B * H + (size_t)brow * H + j;
    fin[fb]     = h0;
    fin[fb + H] = h1;
}

// ---------------------------------------------------------------------------
extern "C" void kernel_launch(void* const* d_in, const int* in_sizes, int n_in,
                              void* d_out, int out_size)
{
    const float* inp = (const float*)d_in[0];
    const float* Wxf = (const float*)d_in[1];
    const float* Whf = (const float*)d_in[2];
    const float* bf  = (const float*)d_in[3];
    const float* Wxb = (const float*)d_in[4];
    const float* Whb = (const float*)d_in[5];
    const float* bb  = (const float*)d_in[6];
    float* out = (float*)d_out;

    cvt_x_kernel<<<TBD / 8 / 256, 256>>>(inp);
    cvt_w_kernel<<<2 * H * (D / 8) / 256, 256>>>(Wxf, Wxb);

    cudaFuncSetAttribute(proj_tc_kernel,
                         cudaFuncAttributeMaxDynamicSharedMemorySize, PROJ_SMEM);
    dim3 g1(T * B / 128, H / 128, 2);
    proj_tc_kernel<<<g1, 256, PROJ_SMEM>>>(bf, bb);

    scan_kernel<<<128, 256>>>(Whf, Whb, out);
}

// round 16
// speedup vs baseline: 1.0164x; 1.0164x over previous
#include <cuda_runtime.h>
#include <cuda_bf16.h>
#include <math.h>

#define T 512
#define B 128
#define D 256
#define H 256
#define TBD (T * B * D)

// Scratch: input projections per direction, bf16 split arrays for proj GEMM.
__device__ float g_xw[2][(size_t)T * B * H];
__device__ uint4 g_xh4[TBD / 8];            // x hi bf16, [m][k] k-major, 8/uint4
__device__ uint4 g_xl4[TBD / 8];            // x lo residual bf16
__device__ uint4 g_wth4[2][H * D / 8];      // W^T hi bf16, [n][k] k-major
__device__ uint4 g_wtl4[2][H * D / 8];      // W^T lo residual

typedef unsigned long long u64;
typedef unsigned int u32;

__device__ __forceinline__ u64 pk2(float lo, float hi) {
    u64 r; asm("mov.b64 %0, {%1, %2};" : "=l"(r) : "f"(lo), "f"(hi)); return r;
}
__device__ __forceinline__ void upk2(float& lo, float& hi, u64 v) {
    asm("mov.b64 {%0, %1}, %2;" : "=f"(lo), "=f"(hi) : "l"(v));
}
__device__ __forceinline__ void ffma2(u64& acc, u64 a, u64 b) {
    asm("fma.rn.f32x2 %0, %1, %2, %3;" : "=l"(acc) : "l"(a), "l"(b), "l"(acc));
}
__device__ __forceinline__ void addf2(u64& a, u64 b) {
    asm("add.rn.f32x2 %0, %1, %2;" : "=l"(a) : "l"(a), "l"(b));
}
__device__ __forceinline__ float tanh_fast(float x) {
    float y; asm("tanh.approx.f32 %0, %1;" : "=f"(y) : "f"(x)); return y;
}
__device__ __forceinline__ u64 bfpair(u32 w) {
    u64 r;
    asm("{ .reg .b32 lo, hi;\n"
        "  shl.b32 lo, %1, 16;\n"
        "  and.b32 hi, %1, 0xffff0000;\n"
        "  mov.b64 %0, {lo, hi}; }" : "=l"(r) : "r"(w));
    return r;
}
// pack two f32 into bf16x2: lo16 = cvt(vlo), hi16 = cvt(vhi)
__device__ __forceinline__ u32 cvt_bf16x2(float vhi, float vlo) {
    u32 d; asm("cvt.rn.bf16x2.f32 %0, %1, %2;" : "=r"(d) : "f"(vhi), "f"(vlo));
    return d;
}
__device__ __forceinline__ void cp_async16(void* smem_dst, const void* gptr) {
    u32 saddr = (u32)__cvta_generic_to_shared(smem_dst);
    asm volatile("cp.async.cg.shared.global [%0], [%1], 16;\n" :: "r"(saddr), "l"(gptr));
}

// mma.sync m16n8k16 row.col bf16 -> f32 accum
__device__ __forceinline__ void mma_bf16(float* c, u32 a0, u32 a1, u32 a2, u32 a3,
                                         u32 b0, u32 b1) {
    asm volatile(
        "mma.sync.aligned.m16n8k16.row.col.f32.bf16.bf16.f32 "
        "{%0,%1,%2,%3}, {%4,%5,%6,%7}, {%8,%9}, {%0,%1,%2,%3};"
        : "+f"(c[0]), "+f"(c[1]), "+f"(c[2]), "+f"(c[3])
        : "r"(a0), "r"(a1), "r"(a2), "r"(a3), "r"(b0), "r"(b1));
}

// ---------------------------------------------------------------------------
// Convert kernels (run once, before proj)
// ---------------------------------------------------------------------------
__global__ __launch_bounds__(256) void cvt_x_kernel(const float* __restrict__ inp)
{
    size_t i = (size_t)blockIdx.x * 256 + threadIdx.x;   // over TBD/8
    const float4* p = (const float4*)inp + i * 2;
    float4 v0 = p[0], v1 = p[1];
    u32 h0 = cvt_bf16x2(v0.y, v0.x);
    u32 h1 = cvt_bf16x2(v0.w, v0.z);
    u32 h2 = cvt_bf16x2(v1.y, v1.x);
    u32 h3 = cvt_bf16x2(v1.w, v1.z);
    u32 l0, l1, l2, l3;
    {
        float a0 = __uint_as_float(h0 << 16), a1 = __uint_as_float(h0 & 0xffff0000u);
        l0 = cvt_bf16x2(v0.y - a1, v0.x - a0);
        float b0 = __uint_as_float(h1 << 16), b1 = __uint_as_float(h1 & 0xffff0000u);
        l1 = cvt_bf16x2(v0.w - b1, v0.z - b0);
        float c0 = __uint_as_float(h2 << 16), c1 = __uint_as_float(h2 & 0xffff0000u);
        l2 = cvt_bf16x2(v1.y - c1, v1.x - c0);
        float d0 = __uint_as_float(h3 << 16), d1 = __uint_as_float(h3 & 0xffff0000u);
        l3 = cvt_bf16x2(v1.w - d1, v1.z - d0);
    }
    g_xh4[i] = make_uint4(h0, h1, h2, h3);
    g_xl4[i] = make_uint4(l0, l1, l2, l3);
}

__global__ __launch_bounds__(256) void cvt_w_kernel(const float* __restrict__ Wf,
                                                    const float* __restrict__ Wb)
{
    int i = blockIdx.x * 256 + threadIdx.x;     // over 2 * H * (D/8)
    const int per = H * (D / 8);
    int dir = i / per;
    int idx = i - dir * per;
    int n  = idx >> 5;          // D/8 = 32
    int kc = idx & 31;
    int k0 = kc * 8;
    const float* W = dir ? Wb : Wf;
    u32 hh[4], ll[4];
    #pragma unroll
    for (int q = 0; q < 4; q++) {
        float w0 = W[(size_t)(k0 + 2 * q) * H + n];
        float w1 = W[(size_t)(k0 + 2 * q + 1) * H + n];
        u32 h = cvt_bf16x2(w1, w0);
        float e0 = __uint_as_float(h << 16);
        float e1 = __uint_as_float(h & 0xffff0000u);
        hh[q] = h;
        ll[q] = cvt_bf16x2(w1 - e1, w0 - e0);
    }
    g_wth4[dir][idx] = make_uint4(hh[0], hh[1], hh[2], hh[3]);
    g_wtl4[dir][idx] = make_uint4(ll[0], ll[1], ll[2], ll[3]);
}

// ---------------------------------------------------------------------------
// Kernel 1: xw = x @ W + b via HMMA bf16 3-term split.
// SINGLE 64KB stage -> 2 CTAs/SM; cross-CTA interleaving hides staging.
// CTA tile 128m x 128n, 8 warps (4M x 2N). Verified swizzle layout.
// ---------------------------------------------------------------------------
#define SM_AH 0
#define SM_AL 16384
#define SM_BH 32768
#define SM_BL 49152
#define PROJ_SMEM 65536               // one stage, 64KB

__device__ __forceinline__ u32 sw_off(int row, int k) {
    return (u32)(row * 128 + (((k >> 3) ^ (row & 7)) << 4) + (k & 7) * 2);
}

__global__ __launch_bounds__(256, 2) void proj_tc_kernel(
    const float* __restrict__ bfp, const float* __restrict__ bbp)
{
    extern __shared__ char smem[];

    const int dir = blockIdx.z;
    const float* __restrict__ bias = dir ? bbp : bfp;
    float* __restrict__ out = g_xw[dir];
    const uint4* __restrict__ wth = g_wth4[dir];
    const uint4* __restrict__ wtl = g_wtl4[dir];

    const int m0  = blockIdx.x * 128;
    const int n0t = blockIdx.y * 128;

    const int tid  = threadIdx.x;
    const int lane = tid & 31;
    const int wid  = tid >> 5;
    const int gid  = lane >> 2;
    const int tig  = lane & 3;
    const int wm   = wid & 3;
    const int wn   = wid >> 2;
    const int rbase = 32 * wm;
    const int nbase = 64 * wn;

    float acc[2][8][4];
    #pragma unroll
    for (int mf = 0; mf < 2; mf++)
        #pragma unroll
        for (int nf = 0; nf < 8; nf++)
            #pragma unroll
            for (int q = 0; q < 4; q++) acc[mf][nf][q] = 0.f;

    for (int c = 0; c < 4; c++) {
        __syncthreads();   // previous chunk's math done before overwrite

        // stage chunk c: 1024 (row, kc) 16B chunks per tile
        #pragma unroll
        for (int i = tid; i < 1024; i += 256) {
            int row = i >> 3, kc = i & 7;
            u32 dst = (u32)(row * 128 + ((kc ^ (row & 7)) << 4));
            size_t srcA = (size_t)(m0 + row) * 32 + c * 8 + kc;
            size_t srcB = (size_t)(n0t + row) * 32 + c * 8 + kc;
            cp_async16(smem + SM_AH + dst, &g_xh4[srcA]);
            cp_async16(smem + SM_AL + dst, &g_xl4[srcA]);
            cp_async16(smem + SM_BH + dst, &wth[srcB]);
            cp_async16(smem + SM_BL + dst, &wtl[srcB]);
        }
        asm volatile("cp.async.commit_group;\n");
        asm volatile("cp.async.wait_group 0;\n");
        __syncthreads();

        #pragma unroll
        for (int ks = 0; ks < 4; ks++) {
            const int k0 = 16 * ks;
            u32 ah[2][4], al[2][4];
            #pragma unroll
            for (int mf = 0; mf < 2; mf++) {
                int r0 = rbase + 16 * mf + gid;
                int r1 = r0 + 8;
                u32 o00 = sw_off(r0, k0 + 2 * tig);
                u32 o10 = sw_off(r1, k0 + 2 * tig);
                u32 o01 = sw_off(r0, k0 + 8 + 2 * tig);
                u32 o11 = sw_off(r1, k0 + 8 + 2 * tig);
                ah[mf][0] = *(const u32*)(smem + SM_AH + o00);
                ah[mf][1] = *(const u32*)(smem + SM_AH + o10);
                ah[mf][2] = *(const u32*)(smem + SM_AH + o01);
                ah[mf][3] = *(const u32*)(smem + SM_AH + o11);
                al[mf][0] = *(const u32*)(smem + SM_AL + o00);
                al[mf][1] = *(const u32*)(smem + SM_AL + o10);
                al[mf][2] = *(const u32*)(smem + SM_AL + o01);
                al[mf][3] = *(const u32*)(smem + SM_AL + o11);
            }
            #pragma unroll
            for (int nf = 0; nf < 8; nf++) {
                int n = nbase + 8 * nf + gid;
                u32 ob0 = sw_off(n, k0 + 2 * tig);
                u32 ob1 = sw_off(n, k0 + 8 + 2 * tig);
                u32 bh0 = *(const u32*)(smem + SM_BH + ob0);
                u32 bh1 = *(const u32*)(smem + SM_BH + ob1);
                u32 bl0 = *(const u32*)(smem + SM_BL + ob0);
                u32 bl1 = *(const u32*)(smem + SM_BL + ob1);
                #pragma unroll
                for (int mf = 0; mf < 2; mf++) {
                    mma_bf16(acc[mf][nf], ah[mf][0], ah[mf][1], ah[mf][2], ah[mf][3], bh0, bh1);
                    mma_bf16(acc[mf][nf], ah[mf][0], ah[mf][1], ah[mf][2], ah[mf][3], bl0, bl1);
                    mma_bf16(acc[mf][nf], al[mf][0], al[mf][1], al[mf][2], al[mf][3], bh0, bh1);
                }
            }
        }
    }

    // epilogue: bias + store
    #pragma unroll
    for (int nf = 0; nf < 8; nf++) {
        int ncol = n0t + nbase + 8 * nf + 2 * tig;
        float2 bv = *(const float2*)&bias[ncol];
        #pragma unroll
        for (int mf = 0; mf < 2; mf++) {
            int row0 = m0 + rbase + 16 * mf + gid;
            int row1 = row0 + 8;
            *(float2*)&out[(size_t)row0 * H + ncol] =
                make_float2(acc[mf][nf][0] + bv.x, acc[mf][nf][1] + bv.y);
            *(float2*)&out[(size_t)row1 * H + ncol] =
                make_float2(acc[mf][nf][2] + bv.x, acc[mf][nf][3] + bv.y);
        }
    }
}

// ---------------------------------------------------------------------------
// Kernel 2: recurrent scan (round-7/14 organization — proven optimum).
// Micro-trims only: running pointers for x/out (no per-step 64-bit muls),
// packed f32x2 accumulator reduction.
// ---------------------------------------------------------------------------
#define NK8 (H / 8)

__global__ __launch_bounds__(256, 1) void scan_kernel(
    const float* __restrict__ Whh_f,
    const float* __restrict__ Whh_b,
    float* __restrict__ out)
{
    __shared__ float hbuf[2 * 2 * H];

    const int blk  = blockIdx.x;
    const int dir  = blk >> 6;
    const int brow = (blk & 63) * 2;
    const float* __restrict__ Whh = dir ? Whh_b : Whh_f;
    const float* __restrict__ xw  = g_xw[dir];
    const int j = threadIdx.x;

    uint4 wreg[NK8];
    #pragma unroll
    for (int k8 = 0; k8 < NK8; k8++) {
        u32 wrd[4];
        #pragma unroll
        for (int q = 0; q < 4; q++) {
            float w0 = Whh[(k8 * 8 + 2 * q)     * H + j];
            float w1 = Whh[(k8 * 8 + 2 * q + 1) * H + j];
            u32 b0 = (u32)__bfloat16_as_ushort(__float2bfloat16(w0));
            u32 b1 = (u32)__bfloat16_as_ushort(__float2bfloat16(w1));
            wrd[q] = (b1 << 16) | b0;
        }
        wreg[k8] = make_uint4(wrd[0], wrd[1], wrd[2], wrd[3]);
    }

    hbuf[j] = 0.f;
    hbuf[H + j] = 0.f;
    __syncthreads();

    float* __restrict__ fin = out + (size_t)T * B * 2 * H;

    const int t0 = dir ? (T - 1) : 0;
    const int dt = dir ? -1 : 1;
    const ptrdiff_t dxw  = (ptrdiff_t)dt * B * H;
    const ptrdiff_t dout = (ptrdiff_t)dt * B * 2 * H;

    // running pointers (hoisted address math)
    const float* xp = xw  + ((size_t)t0 * B + brow) * H + j;
    float*       op = out + ((size_t)t0 * B + brow) * (2 * H) + (size_t)dir * H + j;

    int p = 0;
    float h0 = 0.f, h1 = 0.f;

    float x0 = __ldg(xp);
    float x1 = __ldg(xp + H);
    xp += dxw;

    for (int s = 0; s < T; s++) {
        float xn0 = 0.f, xn1 = 0.f;
        if (s + 1 < T) {
            xn0 = __ldg(xp);
            xn1 = __ldg(xp + H);
        }
        xp += dxw;

        const float* hr0 = hbuf + p * (2 * H);
        const float* hr1 = hr0 + H;

        u64 acc[2][4];
        #pragma unroll
        for (int r = 0; r < 2; r++)
            #pragma unroll
            for (int q = 0; q < 4; q++) acc[r][q] = 0ull;

        #pragma unroll
        for (int k8 = 0; k8 < NK8; k8++) {
            uint4 w = wreg[k8];
            ulonglong2 a0 = *(const ulonglong2*)&hr0[k8 * 8];
            ulonglong2 a1 = *(const ulonglong2*)&hr0[k8 * 8 + 4];
            ulonglong2 b0 = *(const ulonglong2*)&hr1[k8 * 8];
            ulonglong2 b1 = *(const ulonglong2*)&hr1[k8 * 8 + 4];
            u64 w01 = bfpair(w.x);
            u64 w23 = bfpair(w.y);
            u64 w45 = bfpair(w.z);
            u64 w67 = bfpair(w.w);
            ffma2(acc[0][0], a0.x, w01);
            ffma2(acc[0][1], a0.y, w23);
            ffma2(acc[0][2], a1.x, w45);
            ffma2(acc[0][3], a1.y, w67);
            ffma2(acc[1][0], b0.x, w01);
            ffma2(acc[1][1], b0.y, w23);
            ffma2(acc[1][2], b1.x, w45);
            ffma2(acc[1][3], b1.y, w67);
        }

        // packed pairwise reduction: 3 f32x2 adds per row, then one unpack
        addf2(acc[0][0], acc[0][1]);
        addf2(acc[0][2], acc[0][3]);
        addf2(acc[0][0], acc[0][2]);
        addf2(acc[1][0], acc[1][1]);
        addf2(acc[1][2], acc[1][3]);
        addf2(acc[1][0], acc[1][2]);
        float lo, hi;
        upk2(lo, hi, acc[0][0]); float s0 = x0 + lo + hi;
        upk2(lo, hi, acc[1][0]); float s1 = x1 + lo + hi;

        h0 = tanh_fast(s0);
        h1 = tanh_fast(s1);

        hbuf[(p ^ 1) * (2 * H) + j]     = h0;
        hbuf[(p ^ 1) * (2 * H) + H + j] = h1;

        op[0]     = h0;
        op[2 * H] = h1;
        op += dout;

        __syncthreads();
        p ^= 1;
        x0 = xn0;
        x1 = xn1;
    }

    size_t fb = (size_t)dir * B * H + (size_t)brow * H + j;
    fin[fb]     = h0;
    fin[fb + H] = h1;
}

// ---------------------------------------------------------------------------
extern "C" void kernel_launch(void* const* d_in, const int* in_sizes, int n_in,
                              void* d_out, int out_size)
{
    const float* inp = (const float*)d_in[0];
    const float* Wxf = (const float*)d_in[1];
    const float* Whf = (const float*)d_in[2];
    const float* bf  = (const float*)d_in[3];
    const float* Wxb = (const float*)d_in[4];
    const float* Whb = (const float*)d_in[5];
    const float* bb  = (const float*)d_in[6];
    float* out = (float*)d_out;

    cvt_x_kernel<<<TBD / 8 / 256, 256>>>(inp);
    cvt_w_kernel<<<2 * H * (D / 8) / 256, 256>>>(Wxf, Wxb);

    cudaFuncSetAttribute(proj_tc_kernel,
                         cudaFuncAttributeMaxDynamicSharedMemorySize, PROJ_SMEM);
    dim3 g1(T * B / 128, H / 128, 2);
    proj_tc_kernel<<<g1, 256, PROJ_SMEM>>>(bf, bb);

    scan_kernel<<<128, 256>>>(Whf, Whb, out);
}

// round 17
// speedup vs baseline: 1.2079x; 1.1885x over previous
#include <cuda_runtime.h>
#include <cuda_bf16.h>
#include <math.h>

#define T 512
#define B 128
#define D 256
#define H 256
#define TBD (T * B * D)

// Scratch: input projections per direction, bf16 split arrays for proj GEMM.
__device__ float g_xw[2][(size_t)T * B * H];
__device__ uint4 g_xh4[TBD / 8];            // x hi bf16, [m][k] k-major, 8/uint4
__device__ uint4 g_xl4[TBD / 8];            // x lo residual bf16
__device__ uint4 g_wth4[2][H * D / 8];      // W^T hi bf16, [n][k] k-major
__device__ uint4 g_wtl4[2][H * D / 8];      // W^T lo residual

typedef unsigned long long u64;
typedef unsigned int u32;

__device__ __forceinline__ u64 pk2(float lo, float hi) {
    u64 r; asm("mov.b64 %0, {%1, %2};" : "=l"(r) : "f"(lo), "f"(hi)); return r;
}
__device__ __forceinline__ void upk2(float& lo, float& hi, u64 v) {
    asm("mov.b64 {%0, %1}, %2;" : "=f"(lo), "=f"(hi) : "l"(v));
}
__device__ __forceinline__ void ffma2(u64& acc, u64 a, u64 b) {
    asm("fma.rn.f32x2 %0, %1, %2, %3;" : "=l"(acc) : "l"(a), "l"(b), "l"(acc));
}
__device__ __forceinline__ float tanh_fast(float x) {
    float y; asm("tanh.approx.f32 %0, %1;" : "=f"(y) : "f"(x)); return y;
}
__device__ __forceinline__ u64 bfpair(u32 w) {
    u64 r;
    asm("{ .reg .b32 lo, hi;\n"
        "  shl.b32 lo, %1, 16;\n"
        "  and.b32 hi, %1, 0xffff0000;\n"
        "  mov.b64 %0, {lo, hi}; }" : "=l"(r) : "r"(w));
    return r;
}
// pack two f32 into bf16x2: lo16 = cvt(vlo), hi16 = cvt(vhi)
__device__ __forceinline__ u32 cvt_bf16x2(float vhi, float vlo) {
    u32 d; asm("cvt.rn.bf16x2.f32 %0, %1, %2;" : "=r"(d) : "f"(vhi), "f"(vlo));
    return d;
}
__device__ __forceinline__ void cp_async16(void* smem_dst, const void* gptr) {
    u32 saddr = (u32)__cvta_generic_to_shared(smem_dst);
    asm volatile("cp.async.cg.shared.global [%0], [%1], 16;\n" :: "r"(saddr), "l"(gptr));
}

// mma.sync m16n8k16 row.col bf16 -> f32 accum
__device__ __forceinline__ void mma_bf16(float* c, u32 a0, u32 a1, u32 a2, u32 a3,
                                         u32 b0, u32 b1) {
    asm volatile(
        "mma.sync.aligned.m16n8k16.row.col.f32.bf16.bf16.f32 "
        "{%0,%1,%2,%3}, {%4,%5,%6,%7}, {%8,%9}, {%0,%1,%2,%3};"
        : "+f"(c[0]), "+f"(c[1]), "+f"(c[2]), "+f"(c[3])
        : "r"(a0), "r"(a1), "r"(a2), "r"(a3), "r"(b0), "r"(b1));
}

// ---------------------------------------------------------------------------
// Convert kernel (run once, before proj). Merged x + w conversion:
// blocks [0, NXB) handle x; blocks [NXB, NXB+NWB) handle W^T.
// ---------------------------------------------------------------------------
#define NXB (TBD / 8 / 256)                 // 8192 blocks for x
#define NWB (2 * H * (D / 8) / 256)         // 64 blocks for W

__global__ __launch_bounds__(256) void cvt_kernel(
    const float* __restrict__ inp,
    const float* __restrict__ Wf, const float* __restrict__ Wb)
{
    if (blockIdx.x < NXB) {
        size_t i = (size_t)blockIdx.x * 256 + threadIdx.x;   // over TBD/8
        const float4* p = (const float4*)inp + i * 2;
        float4 v0 = p[0], v1 = p[1];
        u32 h0 = cvt_bf16x2(v0.y, v0.x);
        u32 h1 = cvt_bf16x2(v0.w, v0.z);
        u32 h2 = cvt_bf16x2(v1.y, v1.x);
        u32 h3 = cvt_bf16x2(v1.w, v1.z);
        u32 l0, l1, l2, l3;
        {
            float a0 = __uint_as_float(h0 << 16), a1 = __uint_as_float(h0 & 0xffff0000u);
            l0 = cvt_bf16x2(v0.y - a1, v0.x - a0);
            float b0 = __uint_as_float(h1 << 16), b1 = __uint_as_float(h1 & 0xffff0000u);
            l1 = cvt_bf16x2(v0.w - b1, v0.z - b0);
            float c0 = __uint_as_float(h2 << 16), c1 = __uint_as_float(h2 & 0xffff0000u);
            l2 = cvt_bf16x2(v1.y - c1, v1.x - c0);
            float d0 = __uint_as_float(h3 << 16), d1 = __uint_as_float(h3 & 0xffff0000u);
            l3 = cvt_bf16x2(v1.w - d1, v1.z - d0);
        }
        g_xh4[i] = make_uint4(h0, h1, h2, h3);
        g_xl4[i] = make_uint4(l0, l1, l2, l3);
    } else {
        int i = (blockIdx.x - NXB) * 256 + threadIdx.x;   // over 2 * H * (D/8)
        const int per = H * (D / 8);
        int dir = i / per;
        int idx = i - dir * per;
        int n  = idx >> 5;          // D/8 = 32
        int kc = idx & 31;
        int k0 = kc * 8;
        const float* W = dir ? Wb : Wf;
        u32 hh[4], ll[4];
        #pragma unroll
        for (int q = 0; q < 4; q++) {
            float w0 = W[(size_t)(k0 + 2 * q) * H + n];
            float w1 = W[(size_t)(k0 + 2 * q + 1) * H + n];
            u32 h = cvt_bf16x2(w1, w0);
            float e0 = __uint_as_float(h << 16);
            float e1 = __uint_as_float(h & 0xffff0000u);
            hh[q] = h;
            ll[q] = cvt_bf16x2(w1 - e1, w0 - e0);
        }
        g_wth4[dir][idx] = make_uint4(hh[0], hh[1], hh[2], hh[3]);
        g_wtl4[dir][idx] = make_uint4(ll[0], ll[1], ll[2], ll[3]);
    }
}

// ---------------------------------------------------------------------------
// Kernel 1: xw = x @ W + b via HMMA bf16 3-term split.
// SINGLE 64KB stage -> 2 CTAs/SM; cross-CTA interleaving hides staging.
// CTA tile 128m x 128n, 8 warps (4M x 2N). Verified swizzle layout.
// ---------------------------------------------------------------------------
#define SM_AH 0
#define SM_AL 16384
#define SM_BH 32768
#define SM_BL 49152
#define PROJ_SMEM 65536               // one stage, 64KB

__device__ __forceinline__ u32 sw_off(int row, int k) {
    return (u32)(row * 128 + (((k >> 3) ^ (row & 7)) << 4) + (k & 7) * 2);
}

__global__ __launch_bounds__(256, 2) void proj_tc_kernel(
    const float* __restrict__ bfp, const float* __restrict__ bbp)
{
    extern __shared__ char smem[];

    const int dir = blockIdx.z;
    const float* __restrict__ bias = dir ? bbp : bfp;
    float* __restrict__ out = g_xw[dir];
    const uint4* __restrict__ wth = g_wth4[dir];
    const uint4* __restrict__ wtl = g_wtl4[dir];

    const int m0  = blockIdx.x * 128;
    const int n0t = blockIdx.y * 128;

    const int tid  = threadIdx.x;
    const int lane = tid & 31;
    const int wid  = tid >> 5;
    const int gid  = lane >> 2;
    const int tig  = lane & 3;
    const int wm   = wid & 3;
    const int wn   = wid >> 2;
    const int rbase = 32 * wm;
    const int nbase = 64 * wn;

    float acc[2][8][4];
    #pragma unroll
    for (int mf = 0; mf < 2; mf++)
        #pragma unroll
        for (int nf = 0; nf < 8; nf++)
            #pragma unroll
            for (int q = 0; q < 4; q++) acc[mf][nf][q] = 0.f;

    for (int c = 0; c < 4; c++) {
        __syncthreads();   // previous chunk's math done before overwrite

        // stage chunk c: 1024 (row, kc) 16B chunks per tile
        #pragma unroll
        for (int i = tid; i < 1024; i += 256) {
            int row = i >> 3, kc = i & 7;
            u32 dst = (u32)(row * 128 + ((kc ^ (row & 7)) << 4));
            size_t srcA = (size_t)(m0 + row) * 32 + c * 8 + kc;
            size_t srcB = (size_t)(n0t + row) * 32 + c * 8 + kc;
            cp_async16(smem + SM_AH + dst, &g_xh4[srcA]);
            cp_async16(smem + SM_AL + dst, &g_xl4[srcA]);
            cp_async16(smem + SM_BH + dst, &wth[srcB]);
            cp_async16(smem + SM_BL + dst, &wtl[srcB]);
        }
        asm volatile("cp.async.commit_group;\n");
        asm volatile("cp.async.wait_group 0;\n");
        __syncthreads();

        #pragma unroll
        for (int ks = 0; ks < 4; ks++) {
            const int k0 = 16 * ks;
            u32 ah[2][4], al[2][4];
            #pragma unroll
            for (int mf = 0; mf < 2; mf++) {
                int r0 = rbase + 16 * mf + gid;
                int r1 = r0 + 8;
                u32 o00 = sw_off(r0, k0 + 2 * tig);
                u32 o10 = sw_off(r1, k0 + 2 * tig);
                u32 o01 = sw_off(r0, k0 + 8 + 2 * tig);
                u32 o11 = sw_off(r1, k0 + 8 + 2 * tig);
                ah[mf][0] = *(const u32*)(smem + SM_AH + o00);
                ah[mf][1] = *(const u32*)(smem + SM_AH + o10);
                ah[mf][2] = *(const u32*)(smem + SM_AH + o01);
                ah[mf][3] = *(const u32*)(smem + SM_AH + o11);
                al[mf][0] = *(const u32*)(smem + SM_AL + o00);
                al[mf][1] = *(const u32*)(smem + SM_AL + o10);
                al[mf][2] = *(const u32*)(smem + SM_AL + o01);
                al[mf][3] = *(const u32*)(smem + SM_AL + o11);
            }
            #pragma unroll
            for (int nf = 0; nf < 8; nf++) {
                int n = nbase + 8 * nf + gid;
                u32 ob0 = sw_off(n, k0 + 2 * tig);
                u32 ob1 = sw_off(n, k0 + 8 + 2 * tig);
                u32 bh0 = *(const u32*)(smem + SM_BH + ob0);
                u32 bh1 = *(const u32*)(smem + SM_BH + ob1);
                u32 bl0 = *(const u32*)(smem + SM_BL + ob0);
                u32 bl1 = *(const u32*)(smem + SM_BL + ob1);
                #pragma unroll
                for (int mf = 0; mf < 2; mf++) {
                    mma_bf16(acc[mf][nf], ah[mf][0], ah[mf][1], ah[mf][2], ah[mf][3], bh0, bh1);
                    mma_bf16(acc[mf][nf], ah[mf][0], ah[mf][1], ah[mf][2], ah[mf][3], bl0, bl1);
                    mma_bf16(acc[mf][nf], al[mf][0], al[mf][1], al[mf][2], al[mf][3], bh0, bh1);
                }
            }
        }
    }

    // epilogue: bias + store
    #pragma unroll
    for (int nf = 0; nf < 8; nf++) {
        int ncol = n0t + nbase + 8 * nf + 2 * tig;
        float2 bv = *(const float2*)&bias[ncol];
        #pragma unroll
        for (int mf = 0; mf < 2; mf++) {
            int row0 = m0 + rbase + 16 * mf + gid;
            int row1 = row0 + 8;
            *(float2*)&out[(size_t)row0 * H + ncol] =
                make_float2(acc[mf][nf][0] + bv.x, acc[mf][nf][1] + bv.y);
            *(float2*)&out[(size_t)row1 * H + ncol] =
                make_float2(acc[mf][nf][2] + bv.x, acc[mf][nf][3] + bv.y);
        }
    }
}

// ---------------------------------------------------------------------------
// Kernel 2: recurrent scan (round-7/14 organization — proven optimum,
// byte-identical to the 834.5us build; DO NOT TOUCH).
// ---------------------------------------------------------------------------
#define NK8 (H / 8)

__global__ __launch_bounds__(256, 1) void scan_kernel(
    const float* __restrict__ Whh_f,
    const float* __restrict__ Whh_b,
    float* __restrict__ out)
{
    __shared__ float hbuf[2 * 2 * H];

    const int blk  = blockIdx.x;
    const int dir  = blk >> 6;
    const int brow = (blk & 63) * 2;
    const float* __restrict__ Whh = dir ? Whh_b : Whh_f;
    const float* __restrict__ xw  = g_xw[dir];
    const int j = threadIdx.x;

    uint4 wreg[NK8];
    #pragma unroll
    for (int k8 = 0; k8 < NK8; k8++) {
        u32 wrd[4];
        #pragma unroll
        for (int q = 0; q < 4; q++) {
            float w0 = Whh[(k8 * 8 + 2 * q)     * H + j];
            float w1 = Whh[(k8 * 8 + 2 * q + 1) * H + j];
            u32 b0 = (u32)__bfloat16_as_ushort(__float2bfloat16(w0));
            u32 b1 = (u32)__bfloat16_as_ushort(__float2bfloat16(w1));
            wrd[q] = (b1 << 16) | b0;
        }
        wreg[k8] = make_uint4(wrd[0], wrd[1], wrd[2], wrd[3]);
    }

    hbuf[j] = 0.f;
    hbuf[H + j] = 0.f;
    __syncthreads();

    float* __restrict__ fin = out + (size_t)T * B * 2 * H;

    int t  = dir ? (T - 1) : 0;
    const int dt = dir ? -1 : 1;
    int p = 0;
    float h0 = 0.f, h1 = 0.f;

    const float* xr = xw + ((size_t)t * B + brow) * H + j;
    float x0 = __ldg(xr);
    float x1 = __ldg(xr + H);

    for (int s = 0; s < T; s++) {
        float xn0 = 0.f, xn1 = 0.f;
        if (s + 1 < T) {
            const float* xr2 = xw + ((size_t)(t + dt) * B + brow) * H + j;
            xn0 = __ldg(xr2);
            xn1 = __ldg(xr2 + H);
        }

        const float* hr0 = hbuf + p * (2 * H);
        const float* hr1 = hr0 + H;

        u64 acc[2][4];
        #pragma unroll
        for (int r = 0; r < 2; r++)
            #pragma unroll
            for (int q = 0; q < 4; q++) acc[r][q] = 0ull;

        #pragma unroll
        for (int k8 = 0; k8 < NK8; k8++) {
            uint4 w = wreg[k8];
            ulonglong2 a0 = *(const ulonglong2*)&hr0[k8 * 8];
            ulonglong2 a1 = *(const ulonglong2*)&hr0[k8 * 8 + 4];
            ulonglong2 b0 = *(const ulonglong2*)&hr1[k8 * 8];
            ulonglong2 b1 = *(const ulonglong2*)&hr1[k8 * 8 + 4];
            u64 w01 = bfpair(w.x);
            u64 w23 = bfpair(w.y);
            u64 w45 = bfpair(w.z);
            u64 w67 = bfpair(w.w);
            ffma2(acc[0][0], a0.x, w01);
            ffma2(acc[0][1], a0.y, w23);
            ffma2(acc[0][2], a1.x, w45);
            ffma2(acc[0][3], a1.y, w67);
            ffma2(acc[1][0], b0.x, w01);
            ffma2(acc[1][1], b0.y, w23);
            ffma2(acc[1][2], b1.x, w45);
            ffma2(acc[1][3], b1.y, w67);
        }

        float lo, hi;
        upk2(lo, hi, acc[0][0]); float s0 = x0 + lo + hi;
        upk2(lo, hi, acc[0][1]); s0 += lo + hi;
        upk2(lo, hi, acc[0][2]); s0 += lo + hi;
        upk2(lo, hi, acc[0][3]); s0 += lo + hi;
        upk2(lo, hi, acc[1][0]); float s1 = x1 + lo + hi;
        upk2(lo, hi, acc[1][1]); s1 += lo + hi;
        upk2(lo, hi, acc[1][2]); s1 += lo + hi;
        upk2(lo, hi, acc[1][3]); s1 += lo + hi;

        h0 = tanh_fast(s0);
        h1 = tanh_fast(s1);

        hbuf[(p ^ 1) * (2 * H) + j]     = h0;
        hbuf[(p ^ 1) * (2 * H) + H + j] = h1;

        size_t ob = ((size_t)t * B + brow) * (2 * H) + (size_t)dir * H + j;
        out[ob]         = h0;
        out[ob + 2 * H] = h1;

        __syncthreads();
        p ^= 1;
        t += dt;
        x0 = xn0;
        x1 = xn1;
    }

    size_t fb = (size_t)dir * B * H + (size_t)brow * H + j;
    fin[fb]     = h0;
    fin[fb + H] = h1;
}

// ---------------------------------------------------------------------------
extern "C" void kernel_launch(void* const* d_in, const int* in_sizes, int n_in,
                              void* d_out, int out_size)
{
    const float* inp = (const float*)d_in[0];
    const float* Wxf = (const float*)d_in[1];
    const float* Whf = (const float*)d_in[2];
    const float* bf  = (const float*)d_in[3];
    const float* Wxb = (const float*)d_in[4];
    const float* Whb = (const float*)d_in[5];
    const float* bb  = (const float*)d_in[6];
    float* out = (float*)d_out;

    cvt_kernel<<<NXB + NWB, 256>>>(inp, Wxf, Wxb);

    cudaFuncSetAttribute(proj_tc_kernel,
                         cudaFuncAttributeMaxDynamicSharedMemorySize, PROJ_SMEM);
    dim3 g1(T * B / 128, H / 128, 2);
    proj_tc_kernel<<<g1, 256, PROJ_SMEM>>>(bf, bb);

    scan_kernel<<<128, 256>>>(Whf, Whb, out);
}